// round 16
// baseline (speedup 1.0000x reference)
#include <cuda_runtime.h>
#include <cuda_fp16.h>
#include <math.h>

// ---------------------------------------------------------------------------
// ProbAttention — round 16: 4-stage GEMM pipeline + fused dot/cumsum kernel.
//   Q,K: 3-term fp16 split (selection-exact).  V: 1-term fp16 end-to-end.
//   out GEMM: ctx_fp16 x Wo 2-term fp16 split, mma.sync.
// Shapes: B=16, L=2048, D_IN=512, HID=512, H=8, D=64, U=40
// ---------------------------------------------------------------------------

#define B_    16
#define L_    2048
#define DIN_  512
#define HID_  512
#define H_    8
#define D_    64
#define U_    40
#define BH_   (B_ * H_)      // 128
#define MROWS (B_ * L_)      // 32768
#define NSPL  8              // attention KV splits

#define NEG_INF (__int_as_float(0xff800000))

// Scratch (no cudaMalloc allowed): device globals.
__device__ float  g_q[(size_t)MROWS * HID_];
__device__ float  g_k[(size_t)MROWS * HID_];
__device__ __half g_kh[(size_t)MROWS * HID_];
__device__ __half g_vh[(size_t)MROWS * HID_];
__device__ __half g_ctxh[(size_t)MROWS * HID_];
__device__ float  g_dot[BH_ * L_];
__device__ int    g_mtop[BH_ * U_];
// fp16 split operands
__device__ __half g_ah[(size_t)3 * MROWS * DIN_];
__device__ __half g_al[(size_t)2 * MROWS * DIN_];   // lo only for Q,K
__device__ __half g_wh[(size_t)3 * DIN_ * HID_];    // [g][n][k] (W transposed)
__device__ __half g_wl[(size_t)2 * DIN_ * HID_];
__device__ __half g_woh[64 * HID_];                 // Wo^T hi [n][k]
__device__ __half g_wol[64 * HID_];                 // Wo^T lo
// attention split partials
__device__ float g_pm[BH_ * NSPL * U_];
__device__ float g_ps[BH_ * NSPL * U_];
__device__ float g_pacc[(size_t)BH_ * NSPL * U_ * D_];

// ---------------------------------------------------------------------------
// PTX helpers (base-target: ldmatrix + mma.sync + cp.async, sm_80+)
// ---------------------------------------------------------------------------
__device__ __forceinline__ unsigned smem_u32(const void* p) {
    unsigned a;
    asm("{ .reg .u64 t; cvta.to.shared.u64 t, %1; cvt.u32.u64 %0, t; }"
        : "=r"(a) : "l"(p));
    return a;
}

__device__ __forceinline__ void ldsm_x4(unsigned& r0, unsigned& r1,
                                        unsigned& r2, unsigned& r3, unsigned a) {
    asm volatile("ldmatrix.sync.aligned.m8n8.x4.shared.b16 {%0,%1,%2,%3}, [%4];"
                 : "=r"(r0), "=r"(r1), "=r"(r2), "=r"(r3) : "r"(a));
}

__device__ __forceinline__ void mma16816(float* d, const unsigned* a, const unsigned* b) {
    asm volatile(
        "mma.sync.aligned.m16n8k16.row.col.f32.f16.f16.f32 "
        "{%0,%1,%2,%3}, {%4,%5,%6,%7}, {%8,%9}, {%0,%1,%2,%3};"
        : "+f"(d[0]), "+f"(d[1]), "+f"(d[2]), "+f"(d[3])
        : "r"(a[0]), "r"(a[1]), "r"(a[2]), "r"(a[3]), "r"(b[0]), "r"(b[1]));
}

__device__ __forceinline__ void cpa16(unsigned d, const void* s) {
    asm volatile("cp.async.cg.shared.global [%0], [%1], 16;" :: "r"(d), "l"(s));
}

// ---------------------------------------------------------------------------
// Kernel 0a: fp32 -> fp16 hi/lo split of the three input matrices
// ---------------------------------------------------------------------------
__global__ __launch_bounds__(256) void split_in(
    const float* __restrict__ q, const float* __restrict__ k, const float* __restrict__ v)
{
    const int g = blockIdx.y;
    const float* src = (g == 0) ? q : (g == 1) ? k : v;
    size_t base = ((size_t)blockIdx.x * 256 + threadIdx.x) * 4;
    float4 x = *(const float4*)(src + base);
    __half h0 = __float2half_rn(x.x), h1 = __float2half_rn(x.y);
    __half h2 = __float2half_rn(x.z), h3 = __float2half_rn(x.w);
    __half2* ah = (__half2*)(g_ah + (size_t)g * MROWS * DIN_ + base);
    ah[0] = __halves2half2(h0, h1); ah[1] = __halves2half2(h2, h3);
    if (g < 2) {   // lo parts only needed for Q, K (3-term); V is 1-term
        __half l0 = __float2half_rn(x.x - __half2float(h0));
        __half l1 = __float2half_rn(x.y - __half2float(h1));
        __half l2 = __float2half_rn(x.z - __half2float(h2));
        __half l3 = __float2half_rn(x.w - __half2float(h3));
        __half2* al = (__half2*)(g_al + (size_t)g * MROWS * DIN_ + base);
        al[0] = __halves2half2(l0, l1); al[1] = __halves2half2(l2, l3);
    }
}

// ---------------------------------------------------------------------------
// Kernel 0b: weight split + transpose: g_w*[g][n][k] = split(W[k][n])
// ---------------------------------------------------------------------------
__global__ __launch_bounds__(256) void split_w(
    const float* __restrict__ Wq, const float* __restrict__ Wk, const float* __restrict__ Wv)
{
    const int g = blockIdx.y;
    const float* W = (g == 0) ? Wq : (g == 1) ? Wk : Wv;
    int o = blockIdx.x * 256 + threadIdx.x;
    int n = o >> 9, kd = o & 511;
    float x = W[(size_t)kd * HID_ + n];
    __half h = __float2half_rn(x);
    g_wh[(size_t)g * DIN_ * HID_ + o] = h;
    if (g < 2)
        g_wl[(size_t)g * DIN_ * HID_ + o] = __float2half_rn(x - __half2float(h));
}

// ---------------------------------------------------------------------------
// Kernel 0c: Wo split + transpose: g_wo*[n][k] = split(Wo[k][n]), n<64, k<512
// ---------------------------------------------------------------------------
__global__ __launch_bounds__(256) void split_wo(const float* __restrict__ Wo)
{
    int o = blockIdx.x * 256 + threadIdx.x;      // 0..32767
    int n = o >> 9, kd = o & 511;
    float x = Wo[(size_t)kd * 64 + n];
    __half h = __float2half_rn(x);
    g_woh[o] = h;
    g_wol[o] = __float2half_rn(x - __half2float(h));
}

// ---------------------------------------------------------------------------
// Kernel 1: QKV GEMM via mma.sync.  Q,K: K'=1536 (3 terms). V: K'=512 (1 term).
// CTA tile 128x128, 4 warps in 2(M)x2(N), warp tile 64x64 (mma/ldsm = 4.0).
// BK=32, 4-stage cp.async pipeline (3 groups of slack in flight).
// Q out fp32; K out fp32 + fp16 copy (for attn); V out fp16.
// ---------------------------------------------------------------------------
#define GSTAGE_B 20480u
#define GEMM_SMEM (4 * 20480)

__global__ __launch_bounds__(128, 2) void gemm_qkv_mma()
{
    extern __shared__ char sm[];
    const int t    = threadIdx.x;
    const int lane = t & 31;
    const int wid  = t >> 5;
    const int g    = blockIdx.z;
    const size_t m0 = (size_t)blockIdx.y * 128;
    const int    n0 = blockIdx.x * 128;
    const int wm = wid >> 1;      // 0..1 -> M offset wm*64
    const int wn = wid & 1;       // 0..1 -> N offset wn*64
    const int nch = (g == 2) ? 16 : 48;

    const __half* ah = g_ah + (size_t)g * MROWS * DIN_;
    const __half* al = g_al + (size_t)g * MROWS * DIN_;   // unused for g==2
    const __half* wh = g_wh + (size_t)g * DIN_ * HID_;
    const __half* wl = g_wl + (size_t)g * DIN_ * HID_;

    const unsigned smb = smem_u32(sm);

    // loader geometry: 128 threads, rows lrow+{0,32,64,96}, 16B at half-col lcol
    const int lrow = t >> 2;            // 0..31
    const int lcol = (t & 3) * 8;       // 0,8,16,24
    unsigned off[4];
#pragma unroll
    for (int i = 0; i < 4; i++)
        off[i] = (unsigned)((lrow + 32 * i) * 40 + lcol) * 2u;

    auto issue = [&](int c, int st) {
        const int phase = c >> 4;            // 0: Ah*Bh, 1: Ah*Bl, 2: Al*Bh
        const int kk = (c & 15) * 32;
        const __half* A  = (phase == 2) ? al : ah;
        const __half* Bm = (phase == 1) ? wl : wh;
        const unsigned sa = smb + (unsigned)st * GSTAGE_B;
        const unsigned sb = sa + 10240u;
#pragma unroll
        for (int i = 0; i < 4; i++) {
            cpa16(sa + off[i], A + (m0 + lrow + 32 * i) * DIN_ + kk + lcol);
            cpa16(sb + off[i], Bm + (size_t)(n0 + lrow + 32 * i) * DIN_ + kk + lcol);
        }
        asm volatile("cp.async.commit_group;" ::: "memory");
    };

    issue(0, 0);
    issue(1, 1);
    issue(2, 2);

    float acc[4][8][4];
#pragma unroll
    for (int i = 0; i < 4; i++)
#pragma unroll
        for (int j = 0; j < 8; j++)
#pragma unroll
            for (int r = 0; r < 4; r++) acc[i][j][r] = 0.f;

    const unsigned aLd = (unsigned)(wm * 64 + (lane & 15)) * 80u + (unsigned)(lane >> 4) * 16u;
    const unsigned bLd = 10240u + (unsigned)(wn * 64 + (lane & 7) + ((lane >> 4) & 1) * 8) * 80u
                                + (unsigned)((lane >> 3) & 1) * 16u;

    for (int c = 0; c < nch; c++) {
        const int st = c & 3;
        // ensure chunk c's group has completed
        if (c < nch - 2)       asm volatile("cp.async.wait_group 2;" ::: "memory");
        else if (c == nch - 2) asm volatile("cp.async.wait_group 1;" ::: "memory");
        else                   asm volatile("cp.async.wait_group 0;" ::: "memory");
        __syncthreads();
        if (c + 3 < nch) issue(c + 3, (c + 3) & 3);

        const unsigned sbase = smb + (unsigned)st * GSTAGE_B;
        const unsigned aBase = sbase + aLd;
        const unsigned bBase = sbase + bLd;
#pragma unroll
        for (int ks = 0; ks < 2; ks++) {
            unsigned a[4][4];
#pragma unroll
            for (int mi = 0; mi < 4; mi++)
                ldsm_x4(a[mi][0], a[mi][1], a[mi][2], a[mi][3],
                        aBase + (unsigned)mi * 1280u + ks * 32u);
#pragma unroll
            for (int tj2 = 0; tj2 < 4; tj2++) {
                unsigned b[4];
                ldsm_x4(b[0], b[1], b[2], b[3],
                        bBase + (unsigned)tj2 * 1280u + ks * 32u);
#pragma unroll
                for (int mi = 0; mi < 4; mi++) {
                    mma16816(acc[mi][2 * tj2],     a[mi], &b[0]);
                    mma16816(acc[mi][2 * tj2 + 1], a[mi], &b[2]);
                }
            }
        }
    }

    if (g < 2) {
        float* C = g ? g_k : g_q;
#pragma unroll
        for (int mi = 0; mi < 4; mi++) {
#pragma unroll
            for (int nj = 0; nj < 8; nj++) {
                const size_t row = m0 + wm * 64 + mi * 16 + (lane >> 2);
                const int    col = n0 + wn * 64 + nj * 8 + (lane & 3) * 2;
                *(float2*)(C + row * HID_ + col) =
                    make_float2(acc[mi][nj][0], acc[mi][nj][1]);
                *(float2*)(C + (row + 8) * HID_ + col) =
                    make_float2(acc[mi][nj][2], acc[mi][nj][3]);
                if (g == 1) {   // fp16 K copy for the attention kernel
                    *(__half2*)(g_kh + row * HID_ + col) =
                        __halves2half2(__float2half_rn(acc[mi][nj][0]),
                                       __float2half_rn(acc[mi][nj][1]));
                    *(__half2*)(g_kh + (row + 8) * HID_ + col) =
                        __halves2half2(__float2half_rn(acc[mi][nj][2]),
                                       __float2half_rn(acc[mi][nj][3]));
                }
            }
        }
    } else {
#pragma unroll
        for (int mi = 0; mi < 4; mi++) {
#pragma unroll
            for (int nj = 0; nj < 8; nj++) {
                const size_t row = m0 + wm * 64 + mi * 16 + (lane >> 2);
                const int    col = n0 + wn * 64 + nj * 8 + (lane & 3) * 2;
                *(__half2*)(g_vh + row * HID_ + col) =
                    __halves2half2(__float2half_rn(acc[mi][nj][0]),
                                   __float2half_rn(acc[mi][nj][1]));
                *(__half2*)(g_vh + (row + 8) * HID_ + col) =
                    __halves2half2(__float2half_rn(acc[mi][nj][2]),
                                   __float2half_rn(acc[mi][nj][3]));
            }
        }
    }
}

// ---------------------------------------------------------------------------
// Kernel 2: FUSED dot + cumsum (both depend only on the GEMM; independent of
// each other, so they share one launch and overlap on the chip).
//   blocks [0, BH_):      cumsum for bh = blockIdx.x  (1024 threads)
//   blocks [BH_, BH_+8192): dot, one warp per (bh,l)  (32 warps/block)
// ---------------------------------------------------------------------------
#define CSEG   16
#define CSEGL  (L_ / CSEG)   // 128

__global__ __launch_bounds__(1024) void dot_cumsum_kernel(const int* __restrict__ idx)
{
    __shared__ float segsum[CSEG][D_ + 1];

    if (blockIdx.x < BH_) {
        // ----- cumsum: ctx_h = fp16(cumsum(v_h, axis=L)), two-pass scan -----
        const int bh  = blockIdx.x;
        const int t   = threadIdx.x;
        const int d   = t & 63;
        const int seg = t >> 6;

        const __half* vp = g_vh   + (size_t)bh * L_ * D_ + (size_t)seg * CSEGL * D_ + d;
        __half*       cp = g_ctxh + (size_t)bh * L_ * D_ + (size_t)seg * CSEGL * D_ + d;

        float s = 0.f;
#pragma unroll 8
        for (int l = 0; l < CSEGL; l++) s += __half2float(vp[(size_t)l * D_]);

        segsum[seg][d] = s;
        __syncthreads();

        float off = 0.f;
#pragma unroll
        for (int s2 = 0; s2 < CSEG; s2++) {
            if (s2 < seg) off += segsum[s2][d];
        }

        float acc = off;
#pragma unroll 8
        for (int l = 0; l < CSEGL; l++) {
            acc += __half2float(vp[(size_t)l * D_]);
            cp[(size_t)l * D_] = __float2half_rn(acc);
        }
    } else {
        // ----- dot[bh,l] = q[bh,l,:] . k[bh,idx[l],:]  (fp32, selection) -----
        const int gw   = (blockIdx.x - BH_) * 32 + (threadIdx.x >> 5);
        const int lane = threadIdx.x & 31;
        const int l  = gw & (L_ - 1);
        const int bh = gw >> 11;

        const float* qrow = g_q + ((size_t)bh * L_ + l) * D_;
        const float* krow = g_k + ((size_t)bh * L_ + idx[l]) * D_;
        float s = qrow[lane] * krow[lane] + qrow[lane + 32] * krow[lane + 32];
#pragma unroll
        for (int o = 16; o > 0; o >>= 1) s += __shfl_xor_sync(0xffffffffu, s, o);
        if (lane == 0) g_dot[gw] = s;
    }
}

// ---------------------------------------------------------------------------
// Kernel 3: top-U indices of dot[bh,:].  Register-resident iterative argmax.
// ---------------------------------------------------------------------------
__global__ __launch_bounds__(256) void topk_kernel()
{
    const int bh   = blockIdx.x;
    const int t    = threadIdx.x;
    const int lane = t & 31;
    const int w    = t >> 5;

    __shared__ float wv[8];
    __shared__ int   wi[8];
    __shared__ int   s_win;

    float vals[8];
#pragma unroll
    for (int i = 0; i < 8; i++) vals[i] = g_dot[bh * L_ + t + 256 * i];

    for (int p = 0; p < U_; p++) {
        float lv = vals[0]; int li = t;
#pragma unroll
        for (int i = 1; i < 8; i++) {
            if (vals[i] > lv) { lv = vals[i]; li = t + 256 * i; }
        }
#pragma unroll
        for (int o = 16; o > 0; o >>= 1) {
            float ov = __shfl_xor_sync(0xffffffffu, lv, o);
            int   oi = __shfl_xor_sync(0xffffffffu, li, o);
            if (ov > lv || (ov == lv && oi < li)) { lv = ov; li = oi; }
        }
        if (lane == 0) { wv[w] = lv; wi[w] = li; }
        __syncthreads();
        if (t == 0) {
            float bv = wv[0]; int bi = wi[0];
#pragma unroll
            for (int j = 1; j < 8; j++)
                if (wv[j] > bv || (wv[j] == bv && wi[j] < bi)) { bv = wv[j]; bi = wi[j]; }
            g_mtop[bh * U_ + p] = bi;
            s_win = bi;
        }
        __syncthreads();
        const int bi = s_win;
        if ((bi & 255) == t) {
#pragma unroll
            for (int i = 0; i < 8; i++)
                if (t + 256 * i == bi) vals[i] = NEG_INF;
        }
    }
}

// ---------------------------------------------------------------------------
// Kernel 5a: split-KV partial attention.  grid = (BH, NSPL).  K,V fp16 in.
// ---------------------------------------------------------------------------
__global__ __launch_bounds__(256) void attn_part()
{
    const int bh   = blockIdx.x;
    const int sp   = blockIdx.y;
    const int t    = threadIdx.x;
    const int lane = t & 31;
    const int w    = t >> 5;

    __shared__ float qs[U_][D_];
    __shared__ float kst[D_][32];
    __shared__ float vs[32][D_];
    __shared__ float ss[U_][32];
    __shared__ float accs[U_][D_];
    __shared__ float mrow[U_], srow[U_], crow[U_];
    __shared__ int   mt[U_];

    if (t < U_) {
        mt[t]   = g_mtop[bh * U_ + t];
        mrow[t] = NEG_INF;
        srow[t] = 0.f;
    }
    __syncthreads();

    for (int i = t; i < U_ * D_; i += 256) {
        int u = i >> 6, d = i & 63;
        qs[u][d]   = g_q[((size_t)bh * L_ + mt[u]) * D_ + d];
        accs[u][d] = 0.f;
    }

    const __half* kbase = g_kh + (size_t)bh * L_ * D_;
    const __half* vbase = g_vh + (size_t)bh * L_ * D_;

    const int tile0 = sp * (L_ / NSPL / 32);
    const int tile1 = tile0 + (L_ / NSPL / 32);

    for (int tile = tile0; tile < tile1; tile++) {
        const int l0 = tile * 32;
        __syncthreads();
#pragma unroll
        for (int i = 0; i < 2; i++) {
            int f   = t + 256 * i;
            int row = f >> 4;
            int c4  = (f & 15) * 4;
            uint2 hk = *(const uint2*)(kbase + (size_t)(l0 + row) * D_ + c4);
            float2 k01 = __half22float2(*(__half2*)&hk.x);
            float2 k23 = __half22float2(*(__half2*)&hk.y);
            kst[c4 + 0][row] = k01.x;
            kst[c4 + 1][row] = k01.y;
            kst[c4 + 2][row] = k23.x;
            kst[c4 + 3][row] = k23.y;
            uint2 hv = *(const uint2*)(vbase + (size_t)(l0 + row) * D_ + c4);
            float2 v01 = __half22float2(*(__half2*)&hv.x);
            float2 v23 = __half22float2(*(__half2*)&hv.y);
            vs[row][c4 + 0] = v01.x;
            vs[row][c4 + 1] = v01.y;
            vs[row][c4 + 2] = v23.x;
            vs[row][c4 + 3] = v23.y;
        }
        __syncthreads();

        {
            float s0 = 0.f, s1 = 0.f, s2 = 0.f, s3 = 0.f, s4 = 0.f;
#pragma unroll 16
            for (int d = 0; d < D_; d++) {
                float bb = kst[d][lane];
                s0 = fmaf(qs[w][d],      bb, s0);
                s1 = fmaf(qs[w + 8][d],  bb, s1);
                s2 = fmaf(qs[w + 16][d], bb, s2);
                s3 = fmaf(qs[w + 24][d], bb, s3);
                s4 = fmaf(qs[w + 32][d], bb, s4);
            }
            const int lg = l0 + lane;
            ss[w][lane]      = (lg > mt[w])      ? NEG_INF : s0 * 0.125f;
            ss[w + 8][lane]  = (lg > mt[w + 8])  ? NEG_INF : s1 * 0.125f;
            ss[w + 16][lane] = (lg > mt[w + 16]) ? NEG_INF : s2 * 0.125f;
            ss[w + 24][lane] = (lg > mt[w + 24]) ? NEG_INF : s3 * 0.125f;
            ss[w + 32][lane] = (lg > mt[w + 32]) ? NEG_INF : s4 * 0.125f;
        }
        __syncthreads();

#pragma unroll
        for (int j = 0; j < 5; j++) {
            const int u = w + 8 * j;
            float svv = ss[u][lane];
            float tm = svv;
#pragma unroll
            for (int o = 16; o > 0; o >>= 1) tm = fmaxf(tm, __shfl_xor_sync(0xffffffffu, tm, o));
            const float om = mrow[u];
            const float nm = fmaxf(om, tm);
            float p = (nm == NEG_INF) ? 0.f : __expf(svv - nm);
            ss[u][lane] = p;
            float sum = p;
#pragma unroll
            for (int o = 16; o > 0; o >>= 1) sum += __shfl_xor_sync(0xffffffffu, sum, o);
            if (lane == 0) {
                const float c = (nm == NEG_INF) ? 1.f : __expf(om - nm);
                srow[u] = srow[u] * c + sum;
                mrow[u] = nm;
                crow[u] = c;
            }
        }
        __syncthreads();

#pragma unroll
        for (int j = 0; j < 5; j++) {
            const int u = w + 8 * j;
            const float c = crow[u];
            float a0 = accs[u][2 * lane]     * c;
            float a1 = accs[u][2 * lane + 1] * c;
#pragma unroll 8
            for (int l = 0; l < 32; l++) {
                const float p = ss[u][l];
                a0 = fmaf(p, vs[l][2 * lane],     a0);
                a1 = fmaf(p, vs[l][2 * lane + 1], a1);
            }
            accs[u][2 * lane]     = a0;
            accs[u][2 * lane + 1] = a1;
        }
    }
    __syncthreads();

    const int pb = (bh * NSPL + sp) * U_;
    if (t < U_) {
        g_pm[pb + t] = mrow[t];
        g_ps[pb + t] = srow[t];
    }
    for (int i = t; i < U_ * D_; i += 256) {
        int u = i >> 6, d = i & 63;
        g_pacc[(size_t)(pb + u) * D_ + d] = accs[u][d];
    }
}

// ---------------------------------------------------------------------------
// Kernel 5b: merge split partials; scatter fp16 into g_ctxh rows.
// ---------------------------------------------------------------------------
__global__ __launch_bounds__(256) void attn_merge()
{
    const int bh = blockIdx.x;
    const int t  = threadIdx.x;

    __shared__ int   mt[U_];
    __shared__ float sden[U_];
    __shared__ float sc[NSPL][U_];

    if (t < U_) {
        mt[t] = g_mtop[bh * U_ + t];
        float m = NEG_INF;
#pragma unroll
        for (int s = 0; s < NSPL; s++)
            m = fmaxf(m, g_pm[(bh * NSPL + s) * U_ + t]);
        float den = 0.f;
#pragma unroll
        for (int s = 0; s < NSPL; s++) {
            float pm = g_pm[(bh * NSPL + s) * U_ + t];
            float c  = (pm == NEG_INF) ? 0.f : __expf(pm - m);
            sc[s][t] = c;
            den += c * g_ps[(bh * NSPL + s) * U_ + t];
        }
        sden[t] = den;
    }
    __syncthreads();

    for (int i = t; i < U_ * D_; i += 256) {
        int u = i >> 6, d = i & 63;
        float a = 0.f;
#pragma unroll
        for (int s = 0; s < NSPL; s++)
            a += sc[s][u] * g_pacc[(size_t)((bh * NSPL + s) * U_ + u) * D_ + d];
        g_ctxh[((size_t)bh * L_ + mt[u]) * D_ + d] = __float2half_rn(a / sden[u]);
    }
}

// ---------------------------------------------------------------------------
// Kernel 6: out = ctx_h(32768x512) @ Wo (2-term fp16 split, K'=1024), mma.sync.
// CTA tile 128x64, 8 warps 4(M)x2(N), warp tile 32x32, BK=32, 3-stage cp.async.
// ---------------------------------------------------------------------------
#define OSTAGE_B 15360u
#define OUT_SMEM (3 * 15360)

__global__ __launch_bounds__(256, 2) void out_gemm_mma(float* __restrict__ out)
{
    extern __shared__ char sm[];
    const int t    = threadIdx.x;
    const int lane = t & 31;
    const int wid  = t >> 5;
    const size_t m0 = (size_t)blockIdx.x * 128;
    const int wm = wid >> 1;
    const int wn = wid & 1;

    const unsigned smb = smem_u32(sm);

    const int lrow = t >> 2;            // 0..63
    const int lcol = (t & 3) * 8;
    const unsigned aOff0 = (unsigned)(lrow * 40 + lcol) * 2u;
    const unsigned aOff1 = (unsigned)((lrow + 64) * 40 + lcol) * 2u;

    auto issue = [&](int c, int st) {
        const int phase = c >> 4;          // 0: Wo_h, 1: Wo_l
        const int kk = (c & 15) * 32;
        const __half* Bm = phase ? g_wol : g_woh;
        const unsigned sa = smb + (unsigned)st * OSTAGE_B;
        const unsigned sb = sa + 10240u;
        cpa16(sa + aOff0, g_ctxh + (m0 + lrow) * HID_ + kk + lcol);
        cpa16(sa + aOff1, g_ctxh + (m0 + lrow + 64) * HID_ + kk + lcol);
        cpa16(sb + aOff0, Bm + (size_t)lrow * HID_ + kk + lcol);   // 64 rows only
        asm volatile("cp.async.commit_group;" ::: "memory");
    };

    issue(0, 0);
    issue(1, 1);

    float acc[2][4][4];
#pragma unroll
    for (int i = 0; i < 2; i++)
#pragma unroll
        for (int j = 0; j < 4; j++)
#pragma unroll
            for (int r = 0; r < 4; r++) acc[i][j][r] = 0.f;

    const unsigned aLd = (unsigned)(wm * 32 + (lane & 15)) * 80u + (unsigned)(lane >> 4) * 16u;
    const unsigned bLd = 10240u + (unsigned)(wn * 32 + (lane & 7) + ((lane >> 4) & 1) * 8) * 80u
                                + (unsigned)((lane >> 3) & 1) * 16u;

    for (int c = 0; c < 32; c++) {
        const int st = c % 3;
        if (c < 30) asm volatile("cp.async.wait_group 1;" ::: "memory");
        else        asm volatile("cp.async.wait_group 0;" ::: "memory");
        __syncthreads();
        if (c + 2 < 32) issue(c + 2, (c + 2) % 3);

        const unsigned sbase = smb + (unsigned)st * OSTAGE_B;
        const unsigned aBase = sbase + aLd;
        const unsigned bBase = sbase + bLd;
#pragma unroll
        for (int ks = 0; ks < 2; ks++) {
            unsigned a0[4], a1[4];
            ldsm_x4(a0[0], a0[1], a0[2], a0[3], aBase + ks * 32u);
            ldsm_x4(a1[0], a1[1], a1[2], a1[3], aBase + 1280u + ks * 32u);
#pragma unroll
            for (int tj2 = 0; tj2 < 2; tj2++) {
                unsigned b[4];
                ldsm_x4(b[0], b[1], b[2], b[3], bBase + (unsigned)tj2 * 1280u + ks * 32u);
                mma16816(acc[0][2 * tj2],     a0, &b[0]);
                mma16816(acc[1][2 * tj2],     a1, &b[0]);
                mma16816(acc[0][2 * tj2 + 1], a0, &b[2]);
                mma16816(acc[1][2 * tj2 + 1], a1, &b[2]);
            }
        }
    }

#pragma unroll
    for (int ti = 0; ti < 2; ti++) {
#pragma unroll
        for (int tj = 0; tj < 4; tj++) {
            const size_t row = m0 + wm * 32 + ti * 16 + (lane >> 2);
            const int    col = wn * 32 + tj * 8 + (lane & 3) * 2;
            *(float2*)(out + row * 64 + col) =
                make_float2(acc[ti][tj][0], acc[ti][tj][1]);
            *(float2*)(out + (row + 8) * 64 + col) =
                make_float2(acc[ti][tj][2], acc[ti][tj][3]);
        }
    }
}

// ---------------------------------------------------------------------------
extern "C" void kernel_launch(void* const* d_in, const int* in_sizes, int n_in,
                              void* d_out, int out_size)
{
    (void)in_sizes; (void)n_in; (void)out_size;
    const float* q_in = (const float*)d_in[0];
    const float* k_in = (const float*)d_in[1];
    const float* v_in = (const float*)d_in[2];
    const float* Wq   = (const float*)d_in[3];
    const float* Wk   = (const float*)d_in[4];
    const float* Wv   = (const float*)d_in[5];
    const float* Wo   = (const float*)d_in[6];
    const int*   idx  = (const int*)d_in[7];
    float* out = (float*)d_out;

    cudaFuncSetAttribute(gemm_qkv_mma,
                         cudaFuncAttributeMaxDynamicSharedMemorySize, GEMM_SMEM);
    cudaFuncSetAttribute(out_gemm_mma,
                         cudaFuncAttributeMaxDynamicSharedMemorySize, OUT_SMEM);

    split_in<<<dim3(MROWS * DIN_ / (4 * 256), 3), 256>>>(q_in, k_in, v_in);
    split_w<<<dim3(DIN_ * HID_ / 256, 3), 256>>>(Wq, Wk, Wv);
    split_wo<<<64 * HID_ / 256, 256>>>(Wo);
    gemm_qkv_mma<<<dim3(HID_ / 128, MROWS / 128, 3), 128, GEMM_SMEM>>>();
    dot_cumsum_kernel<<<BH_ + (BH_ * L_) / 32, 1024>>>(idx);
    topk_kernel<<<BH_, 256>>>();
    attn_part<<<dim3(BH_, NSPL), 256>>>();
    attn_merge<<<BH_, 256>>>();
    out_gemm_mma<<<MROWS / 128, 256, OUT_SMEM>>>(out);
}

// round 17
// speedup vs baseline: 1.0291x; 1.0291x over previous
#include <cuda_runtime.h>
#include <cuda_fp16.h>
#include <math.h>

// ---------------------------------------------------------------------------
// ProbAttention — round 17: R15 baseline (763.9µs) + Wo 1-term fp16 out GEMM
// + fused weight-split launch.
//   Q,K: 3-term fp16 split (selection-exact).  V: 1-term fp16 end-to-end.
// Shapes: B=16, L=2048, D_IN=512, HID=512, H=8, D=64, U=40
// ---------------------------------------------------------------------------

#define B_    16
#define L_    2048
#define DIN_  512
#define HID_  512
#define H_    8
#define D_    64
#define U_    40
#define BH_   (B_ * H_)      // 128
#define MROWS (B_ * L_)      // 32768
#define NSPL  8              // attention KV splits

#define NEG_INF (__int_as_float(0xff800000))

// Scratch (no cudaMalloc allowed): device globals.
__device__ float  g_q[(size_t)MROWS * HID_];
__device__ float  g_k[(size_t)MROWS * HID_];
__device__ __half g_kh[(size_t)MROWS * HID_];
__device__ __half g_vh[(size_t)MROWS * HID_];
__device__ __half g_ctxh[(size_t)MROWS * HID_];
__device__ float  g_dot[BH_ * L_];
__device__ int    g_mtop[BH_ * U_];
// fp16 split operands
__device__ __half g_ah[(size_t)3 * MROWS * DIN_];
__device__ __half g_al[(size_t)2 * MROWS * DIN_];   // lo only for Q,K
__device__ __half g_wh[(size_t)3 * DIN_ * HID_];    // [g][n][k] (W transposed)
__device__ __half g_wl[(size_t)2 * DIN_ * HID_];
__device__ __half g_woh[64 * HID_];                 // Wo^T hi [n][k] (1-term)
// attention split partials
__device__ float g_pm[BH_ * NSPL * U_];
__device__ float g_ps[BH_ * NSPL * U_];
__device__ float g_pacc[(size_t)BH_ * NSPL * U_ * D_];

// ---------------------------------------------------------------------------
// PTX helpers (base-target: ldmatrix + mma.sync + cp.async, sm_80+)
// ---------------------------------------------------------------------------
__device__ __forceinline__ unsigned smem_u32(const void* p) {
    unsigned a;
    asm("{ .reg .u64 t; cvta.to.shared.u64 t, %1; cvt.u32.u64 %0, t; }"
        : "=r"(a) : "l"(p));
    return a;
}

__device__ __forceinline__ void ldsm_x4(unsigned& r0, unsigned& r1,
                                        unsigned& r2, unsigned& r3, unsigned a) {
    asm volatile("ldmatrix.sync.aligned.m8n8.x4.shared.b16 {%0,%1,%2,%3}, [%4];"
                 : "=r"(r0), "=r"(r1), "=r"(r2), "=r"(r3) : "r"(a));
}

__device__ __forceinline__ void mma16816(float* d, const unsigned* a, const unsigned* b) {
    asm volatile(
        "mma.sync.aligned.m16n8k16.row.col.f32.f16.f16.f32 "
        "{%0,%1,%2,%3}, {%4,%5,%6,%7}, {%8,%9}, {%0,%1,%2,%3};"
        : "+f"(d[0]), "+f"(d[1]), "+f"(d[2]), "+f"(d[3])
        : "r"(a[0]), "r"(a[1]), "r"(a[2]), "r"(a[3]), "r"(b[0]), "r"(b[1]));
}

__device__ __forceinline__ void cpa16(unsigned d, const void* s) {
    asm volatile("cp.async.cg.shared.global [%0], [%1], 16;" :: "r"(d), "l"(s));
}

// ---------------------------------------------------------------------------
// Kernel 0a: fp32 -> fp16 hi/lo split of the three input matrices
// ---------------------------------------------------------------------------
__global__ __launch_bounds__(256) void split_in(
    const float* __restrict__ q, const float* __restrict__ k, const float* __restrict__ v)
{
    const int g = blockIdx.y;
    const float* src = (g == 0) ? q : (g == 1) ? k : v;
    size_t base = ((size_t)blockIdx.x * 256 + threadIdx.x) * 4;
    float4 x = *(const float4*)(src + base);
    __half h0 = __float2half_rn(x.x), h1 = __float2half_rn(x.y);
    __half h2 = __float2half_rn(x.z), h3 = __float2half_rn(x.w);
    __half2* ah = (__half2*)(g_ah + (size_t)g * MROWS * DIN_ + base);
    ah[0] = __halves2half2(h0, h1); ah[1] = __halves2half2(h2, h3);
    if (g < 2) {   // lo parts only needed for Q, K (3-term); V is 1-term
        __half l0 = __float2half_rn(x.x - __half2float(h0));
        __half l1 = __float2half_rn(x.y - __half2float(h1));
        __half l2 = __float2half_rn(x.z - __half2float(h2));
        __half l3 = __float2half_rn(x.w - __half2float(h3));
        __half2* al = (__half2*)(g_al + (size_t)g * MROWS * DIN_ + base);
        al[0] = __halves2half2(l0, l1); al[1] = __halves2half2(l2, l3);
    }
}

// ---------------------------------------------------------------------------
// Kernel 0b: weight split + transpose.  g in {0,1,2}: g_w*[g][n][k] = split(W[k][n])
// g == 3: Wo 1-term: g_woh[n][k] = fp16(Wo[k][n])  (only first 32768 elems)
// ---------------------------------------------------------------------------
__global__ __launch_bounds__(256) void split_w(
    const float* __restrict__ Wq, const float* __restrict__ Wk,
    const float* __restrict__ Wv, const float* __restrict__ Wo)
{
    const int g = blockIdx.y;
    int o = blockIdx.x * 256 + threadIdx.x;
    if (g == 3) {
        if (o >= 64 * HID_) return;
        int n = o >> 9, kd = o & 511;
        g_woh[o] = __float2half_rn(Wo[(size_t)kd * 64 + n]);
        return;
    }
    const float* W = (g == 0) ? Wq : (g == 1) ? Wk : Wv;
    int n = o >> 9, kd = o & 511;
    float x = W[(size_t)kd * HID_ + n];
    __half h = __float2half_rn(x);
    g_wh[(size_t)g * DIN_ * HID_ + o] = h;
    if (g < 2)
        g_wl[(size_t)g * DIN_ * HID_ + o] = __float2half_rn(x - __half2float(h));
}

// ---------------------------------------------------------------------------
// Kernel 1: QKV GEMM via mma.sync.  Q,K: K'=1536 (3 terms). V: K'=512 (1 term).
// CTA tile 128x128, 4 warps in 2(M)x2(N), warp tile 64x64 (mma/ldsm = 4.0).
// BK=32, 3-stage cp.async pipeline (measured-best config).
// Q out fp32; K out fp32 + fp16 copy (for attn); V out fp16.
// ---------------------------------------------------------------------------
#define GSTAGE_B 20480u
#define GEMM_SMEM (3 * 20480)

__global__ __launch_bounds__(128, 2) void gemm_qkv_mma()
{
    extern __shared__ char sm[];
    const int t    = threadIdx.x;
    const int lane = t & 31;
    const int wid  = t >> 5;
    const int g    = blockIdx.z;
    const size_t m0 = (size_t)blockIdx.y * 128;
    const int    n0 = blockIdx.x * 128;
    const int wm = wid >> 1;      // 0..1 -> M offset wm*64
    const int wn = wid & 1;       // 0..1 -> N offset wn*64
    const int nch = (g == 2) ? 16 : 48;

    const __half* ah = g_ah + (size_t)g * MROWS * DIN_;
    const __half* al = g_al + (size_t)g * MROWS * DIN_;   // unused for g==2
    const __half* wh = g_wh + (size_t)g * DIN_ * HID_;
    const __half* wl = g_wl + (size_t)g * DIN_ * HID_;

    const unsigned smb = smem_u32(sm);

    // loader geometry: 128 threads, rows lrow+{0,32,64,96}, 16B at half-col lcol
    const int lrow = t >> 2;            // 0..31
    const int lcol = (t & 3) * 8;       // 0,8,16,24
    unsigned off[4];
#pragma unroll
    for (int i = 0; i < 4; i++)
        off[i] = (unsigned)((lrow + 32 * i) * 40 + lcol) * 2u;

    auto issue = [&](int c, int st) {
        const int phase = c >> 4;            // 0: Ah*Bh, 1: Ah*Bl, 2: Al*Bh
        const int kk = (c & 15) * 32;
        const __half* A  = (phase == 2) ? al : ah;
        const __half* Bm = (phase == 1) ? wl : wh;
        const unsigned sa = smb + (unsigned)st * GSTAGE_B;
        const unsigned sb = sa + 10240u;
#pragma unroll
        for (int i = 0; i < 4; i++) {
            cpa16(sa + off[i], A + (m0 + lrow + 32 * i) * DIN_ + kk + lcol);
            cpa16(sb + off[i], Bm + (size_t)(n0 + lrow + 32 * i) * DIN_ + kk + lcol);
        }
        asm volatile("cp.async.commit_group;" ::: "memory");
    };

    issue(0, 0);
    issue(1, 1);

    float acc[4][8][4];
#pragma unroll
    for (int i = 0; i < 4; i++)
#pragma unroll
        for (int j = 0; j < 8; j++)
#pragma unroll
            for (int r = 0; r < 4; r++) acc[i][j][r] = 0.f;

    const unsigned aLd = (unsigned)(wm * 64 + (lane & 15)) * 80u + (unsigned)(lane >> 4) * 16u;
    const unsigned bLd = 10240u + (unsigned)(wn * 64 + (lane & 7) + ((lane >> 4) & 1) * 8) * 80u
                                + (unsigned)((lane >> 3) & 1) * 16u;

    for (int c = 0; c < nch; c++) {
        const int st = c % 3;
        if (c < nch - 2) asm volatile("cp.async.wait_group 1;" ::: "memory");
        else             asm volatile("cp.async.wait_group 0;" ::: "memory");
        __syncthreads();
        if (c + 2 < nch) issue(c + 2, (c + 2) % 3);

        const unsigned sbase = smb + (unsigned)st * GSTAGE_B;
        const unsigned aBase = sbase + aLd;
        const unsigned bBase = sbase + bLd;
#pragma unroll
        for (int ks = 0; ks < 2; ks++) {
            unsigned a[4][4];
#pragma unroll
            for (int mi = 0; mi < 4; mi++)
                ldsm_x4(a[mi][0], a[mi][1], a[mi][2], a[mi][3],
                        aBase + (unsigned)mi * 1280u + ks * 32u);
#pragma unroll
            for (int tj2 = 0; tj2 < 4; tj2++) {
                unsigned b[4];
                ldsm_x4(b[0], b[1], b[2], b[3],
                        bBase + (unsigned)tj2 * 1280u + ks * 32u);
#pragma unroll
                for (int mi = 0; mi < 4; mi++) {
                    mma16816(acc[mi][2 * tj2],     a[mi], &b[0]);
                    mma16816(acc[mi][2 * tj2 + 1], a[mi], &b[2]);
                }
            }
        }
    }

    if (g < 2) {
        float* C = g ? g_k : g_q;
#pragma unroll
        for (int mi = 0; mi < 4; mi++) {
#pragma unroll
            for (int nj = 0; nj < 8; nj++) {
                const size_t row = m0 + wm * 64 + mi * 16 + (lane >> 2);
                const int    col = n0 + wn * 64 + nj * 8 + (lane & 3) * 2;
                *(float2*)(C + row * HID_ + col) =
                    make_float2(acc[mi][nj][0], acc[mi][nj][1]);
                *(float2*)(C + (row + 8) * HID_ + col) =
                    make_float2(acc[mi][nj][2], acc[mi][nj][3]);
                if (g == 1) {   // fp16 K copy for the attention kernel
                    *(__half2*)(g_kh + row * HID_ + col) =
                        __halves2half2(__float2half_rn(acc[mi][nj][0]),
                                       __float2half_rn(acc[mi][nj][1]));
                    *(__half2*)(g_kh + (row + 8) * HID_ + col) =
                        __halves2half2(__float2half_rn(acc[mi][nj][2]),
                                       __float2half_rn(acc[mi][nj][3]));
                }
            }
        }
    } else {
#pragma unroll
        for (int mi = 0; mi < 4; mi++) {
#pragma unroll
            for (int nj = 0; nj < 8; nj++) {
                const size_t row = m0 + wm * 64 + mi * 16 + (lane >> 2);
                const int    col = n0 + wn * 64 + nj * 8 + (lane & 3) * 2;
                *(__half2*)(g_vh + row * HID_ + col) =
                    __halves2half2(__float2half_rn(acc[mi][nj][0]),
                                   __float2half_rn(acc[mi][nj][1]));
                *(__half2*)(g_vh + (row + 8) * HID_ + col) =
                    __halves2half2(__float2half_rn(acc[mi][nj][2]),
                                   __float2half_rn(acc[mi][nj][3]));
            }
        }
    }
}

// ---------------------------------------------------------------------------
// Kernel 2: dot[bh,l] = q[bh,l,:] . k[bh,idx[l],:]   (fp32 — feeds selection)
// ---------------------------------------------------------------------------
__global__ __launch_bounds__(256) void dot_kernel(const int* __restrict__ idx)
{
    const int gid  = blockIdx.x * blockDim.x + threadIdx.x;
    const int warp = gid >> 5;
    const int lane = gid & 31;
    const int l  = warp & (L_ - 1);
    const int bh = warp >> 11;

    const float* qrow = g_q + ((size_t)bh * L_ + l) * D_;
    const float* krow = g_k + ((size_t)bh * L_ + idx[l]) * D_;
    float s = qrow[lane] * krow[lane] + qrow[lane + 32] * krow[lane + 32];
#pragma unroll
    for (int o = 16; o > 0; o >>= 1) s += __shfl_xor_sync(0xffffffffu, s, o);
    if (lane == 0) g_dot[warp] = s;
}

// ---------------------------------------------------------------------------
// Kernel 3: top-U indices of dot[bh,:].  Register-resident iterative argmax.
// ---------------------------------------------------------------------------
__global__ __launch_bounds__(256) void topk_kernel()
{
    const int bh   = blockIdx.x;
    const int t    = threadIdx.x;
    const int lane = t & 31;
    const int w    = t >> 5;

    __shared__ float wv[8];
    __shared__ int   wi[8];
    __shared__ int   s_win;

    float vals[8];
#pragma unroll
    for (int i = 0; i < 8; i++) vals[i] = g_dot[bh * L_ + t + 256 * i];

    for (int p = 0; p < U_; p++) {
        float lv = vals[0]; int li = t;
#pragma unroll
        for (int i = 1; i < 8; i++) {
            if (vals[i] > lv) { lv = vals[i]; li = t + 256 * i; }
        }
#pragma unroll
        for (int o = 16; o > 0; o >>= 1) {
            float ov = __shfl_xor_sync(0xffffffffu, lv, o);
            int   oi = __shfl_xor_sync(0xffffffffu, li, o);
            if (ov > lv || (ov == lv && oi < li)) { lv = ov; li = oi; }
        }
        if (lane == 0) { wv[w] = lv; wi[w] = li; }
        __syncthreads();
        if (t == 0) {
            float bv = wv[0]; int bi = wi[0];
#pragma unroll
            for (int j = 1; j < 8; j++)
                if (wv[j] > bv || (wv[j] == bv && wi[j] < bi)) { bv = wv[j]; bi = wi[j]; }
            g_mtop[bh * U_ + p] = bi;
            s_win = bi;
        }
        __syncthreads();
        const int bi = s_win;
        if ((bi & 255) == t) {
#pragma unroll
            for (int i = 0; i < 8; i++)
                if (t + 256 * i == bi) vals[i] = NEG_INF;
        }
    }
}

// ---------------------------------------------------------------------------
// Kernel 4: ctx_h = fp16(cumsum(v_h, axis=L)).  Parallel two-pass scan.
// ---------------------------------------------------------------------------
#define CSEG   16
#define CSEGL  (L_ / CSEG)   // 128

__global__ __launch_bounds__(1024) void cumsum_kernel()
{
    const int bh  = blockIdx.x;
    const int t   = threadIdx.x;
    const int d   = t & 63;
    const int seg = t >> 6;

    const __half* vp = g_vh   + (size_t)bh * L_ * D_ + (size_t)seg * CSEGL * D_ + d;
    __half*       cp = g_ctxh + (size_t)bh * L_ * D_ + (size_t)seg * CSEGL * D_ + d;

    float s = 0.f;
#pragma unroll 8
    for (int l = 0; l < CSEGL; l++) s += __half2float(vp[(size_t)l * D_]);

    __shared__ float segsum[CSEG][D_ + 1];
    segsum[seg][d] = s;
    __syncthreads();

    float off = 0.f;
#pragma unroll
    for (int s2 = 0; s2 < CSEG; s2++) {
        if (s2 < seg) off += segsum[s2][d];
    }

    float acc = off;
#pragma unroll 8
    for (int l = 0; l < CSEGL; l++) {
        acc += __half2float(vp[(size_t)l * D_]);
        cp[(size_t)l * D_] = __float2half_rn(acc);
    }
}

// ---------------------------------------------------------------------------
// Kernel 5a: split-KV partial attention.  grid = (BH, NSPL).  K,V fp16 in.
// ---------------------------------------------------------------------------
__global__ __launch_bounds__(256) void attn_part()
{
    const int bh   = blockIdx.x;
    const int sp   = blockIdx.y;
    const int t    = threadIdx.x;
    const int lane = t & 31;
    const int w    = t >> 5;

    __shared__ float qs[U_][D_];
    __shared__ float kst[D_][32];
    __shared__ float vs[32][D_];
    __shared__ float ss[U_][32];
    __shared__ float accs[U_][D_];
    __shared__ float mrow[U_], srow[U_], crow[U_];
    __shared__ int   mt[U_];

    if (t < U_) {
        mt[t]   = g_mtop[bh * U_ + t];
        mrow[t] = NEG_INF;
        srow[t] = 0.f;
    }
    __syncthreads();

    for (int i = t; i < U_ * D_; i += 256) {
        int u = i >> 6, d = i & 63;
        qs[u][d]   = g_q[((size_t)bh * L_ + mt[u]) * D_ + d];
        accs[u][d] = 0.f;
    }

    const __half* kbase = g_kh + (size_t)bh * L_ * D_;
    const __half* vbase = g_vh + (size_t)bh * L_ * D_;

    const int tile0 = sp * (L_ / NSPL / 32);
    const int tile1 = tile0 + (L_ / NSPL / 32);

    for (int tile = tile0; tile < tile1; tile++) {
        const int l0 = tile * 32;
        __syncthreads();
#pragma unroll
        for (int i = 0; i < 2; i++) {
            int f   = t + 256 * i;
            int row = f >> 4;
            int c4  = (f & 15) * 4;
            uint2 hk = *(const uint2*)(kbase + (size_t)(l0 + row) * D_ + c4);
            float2 k01 = __half22float2(*(__half2*)&hk.x);
            float2 k23 = __half22float2(*(__half2*)&hk.y);
            kst[c4 + 0][row] = k01.x;
            kst[c4 + 1][row] = k01.y;
            kst[c4 + 2][row] = k23.x;
            kst[c4 + 3][row] = k23.y;
            uint2 hv = *(const uint2*)(vbase + (size_t)(l0 + row) * D_ + c4);
            float2 v01 = __half22float2(*(__half2*)&hv.x);
            float2 v23 = __half22float2(*(__half2*)&hv.y);
            vs[row][c4 + 0] = v01.x;
            vs[row][c4 + 1] = v01.y;
            vs[row][c4 + 2] = v23.x;
            vs[row][c4 + 3] = v23.y;
        }
        __syncthreads();

        {
            float s0 = 0.f, s1 = 0.f, s2 = 0.f, s3 = 0.f, s4 = 0.f;
#pragma unroll 16
            for (int d = 0; d < D_; d++) {
                float bb = kst[d][lane];
                s0 = fmaf(qs[w][d],      bb, s0);
                s1 = fmaf(qs[w + 8][d],  bb, s1);
                s2 = fmaf(qs[w + 16][d], bb, s2);
                s3 = fmaf(qs[w + 24][d], bb, s3);
                s4 = fmaf(qs[w + 32][d], bb, s4);
            }
            const int lg = l0 + lane;
            ss[w][lane]      = (lg > mt[w])      ? NEG_INF : s0 * 0.125f;
            ss[w + 8][lane]  = (lg > mt[w + 8])  ? NEG_INF : s1 * 0.125f;
            ss[w + 16][lane] = (lg > mt[w + 16]) ? NEG_INF : s2 * 0.125f;
            ss[w + 24][lane] = (lg > mt[w + 24]) ? NEG_INF : s3 * 0.125f;
            ss[w + 32][lane] = (lg > mt[w + 32]) ? NEG_INF : s4 * 0.125f;
        }
        __syncthreads();

#pragma unroll
        for (int j = 0; j < 5; j++) {
            const int u = w + 8 * j;
            float svv = ss[u][lane];
            float tm = svv;
#pragma unroll
            for (int o = 16; o > 0; o >>= 1) tm = fmaxf(tm, __shfl_xor_sync(0xffffffffu, tm, o));
            const float om = mrow[u];
            const float nm = fmaxf(om, tm);
            float p = (nm == NEG_INF) ? 0.f : __expf(svv - nm);
            ss[u][lane] = p;
            float sum = p;
#pragma unroll
            for (int o = 16; o > 0; o >>= 1) sum += __shfl_xor_sync(0xffffffffu, sum, o);
            if (lane == 0) {
                const float c = (nm == NEG_INF) ? 1.f : __expf(om - nm);
                srow[u] = srow[u] * c + sum;
                mrow[u] = nm;
                crow[u] = c;
            }
        }
        __syncthreads();

#pragma unroll
        for (int j = 0; j < 5; j++) {
            const int u = w + 8 * j;
            const float c = crow[u];
            float a0 = accs[u][2 * lane]     * c;
            float a1 = accs[u][2 * lane + 1] * c;
#pragma unroll 8
            for (int l = 0; l < 32; l++) {
                const float p = ss[u][l];
                a0 = fmaf(p, vs[l][2 * lane],     a0);
                a1 = fmaf(p, vs[l][2 * lane + 1], a1);
            }
            accs[u][2 * lane]     = a0;
            accs[u][2 * lane + 1] = a1;
        }
    }
    __syncthreads();

    const int pb = (bh * NSPL + sp) * U_;
    if (t < U_) {
        g_pm[pb + t] = mrow[t];
        g_ps[pb + t] = srow[t];
    }
    for (int i = t; i < U_ * D_; i += 256) {
        int u = i >> 6, d = i & 63;
        g_pacc[(size_t)(pb + u) * D_ + d] = accs[u][d];
    }
}

// ---------------------------------------------------------------------------
// Kernel 5b: merge split partials; scatter fp16 into g_ctxh rows.
// ---------------------------------------------------------------------------
__global__ __launch_bounds__(256) void attn_merge()
{
    const int bh = blockIdx.x;
    const int t  = threadIdx.x;

    __shared__ int   mt[U_];
    __shared__ float sden[U_];
    __shared__ float sc[NSPL][U_];

    if (t < U_) {
        mt[t] = g_mtop[bh * U_ + t];
        float m = NEG_INF;
#pragma unroll
        for (int s = 0; s < NSPL; s++)
            m = fmaxf(m, g_pm[(bh * NSPL + s) * U_ + t]);
        float den = 0.f;
#pragma unroll
        for (int s = 0; s < NSPL; s++) {
            float pm = g_pm[(bh * NSPL + s) * U_ + t];
            float c  = (pm == NEG_INF) ? 0.f : __expf(pm - m);
            sc[s][t] = c;
            den += c * g_ps[(bh * NSPL + s) * U_ + t];
        }
        sden[t] = den;
    }
    __syncthreads();

    for (int i = t; i < U_ * D_; i += 256) {
        int u = i >> 6, d = i & 63;
        float a = 0.f;
#pragma unroll
        for (int s = 0; s < NSPL; s++)
            a += sc[s][u] * g_pacc[(size_t)((bh * NSPL + s) * U_ + u) * D_ + d];
        g_ctxh[((size_t)bh * L_ + mt[u]) * D_ + d] = __float2half_rn(a / sden[u]);
    }
}

// ---------------------------------------------------------------------------
// Kernel 6: out = ctx_h(32768x512) @ Wo_h (1-term fp16, K'=512), mma.sync.
// CTA tile 128x64, 8 warps 4(M)x2(N), warp tile 32x32, BK=32, 3-stage cp.async.
// ---------------------------------------------------------------------------
#define OSTAGE_B 15360u
#define OUT_SMEM (3 * 15360)

__global__ __launch_bounds__(256, 2) void out_gemm_mma(float* __restrict__ out)
{
    extern __shared__ char sm[];
    const int t    = threadIdx.x;
    const int lane = t & 31;
    const int wid  = t >> 5;
    const size_t m0 = (size_t)blockIdx.x * 128;
    const int wm = wid >> 1;
    const int wn = wid & 1;

    const unsigned smb = smem_u32(sm);

    const int lrow = t >> 2;            // 0..63
    const int lcol = (t & 3) * 8;
    const unsigned aOff0 = (unsigned)(lrow * 40 + lcol) * 2u;
    const unsigned aOff1 = (unsigned)((lrow + 64) * 40 + lcol) * 2u;

    auto issue = [&](int c, int st) {
        const int kk = c * 32;
        const unsigned sa = smb + (unsigned)st * OSTAGE_B;
        const unsigned sb = sa + 10240u;
        cpa16(sa + aOff0, g_ctxh + (m0 + lrow) * HID_ + kk + lcol);
        cpa16(sa + aOff1, g_ctxh + (m0 + lrow + 64) * HID_ + kk + lcol);
        cpa16(sb + aOff0, g_woh + (size_t)lrow * HID_ + kk + lcol);   // 64 rows only
        asm volatile("cp.async.commit_group;" ::: "memory");
    };

    issue(0, 0);
    issue(1, 1);

    float acc[2][4][4];
#pragma unroll
    for (int i = 0; i < 2; i++)
#pragma unroll
        for (int j = 0; j < 4; j++)
#pragma unroll
            for (int r = 0; r < 4; r++) acc[i][j][r] = 0.f;

    const unsigned aLd = (unsigned)(wm * 32 + (lane & 15)) * 80u + (unsigned)(lane >> 4) * 16u;
    const unsigned bLd = 10240u + (unsigned)(wn * 32 + (lane & 7) + ((lane >> 4) & 1) * 8) * 80u
                                + (unsigned)((lane >> 3) & 1) * 16u;

    for (int c = 0; c < 16; c++) {
        const int st = c % 3;
        if (c < 14) asm volatile("cp.async.wait_group 1;" ::: "memory");
        else        asm volatile("cp.async.wait_group 0;" ::: "memory");
        __syncthreads();
        if (c + 2 < 16) issue(c + 2, (c + 2) % 3);

        const unsigned sbase = smb + (unsigned)st * OSTAGE_B;
        const unsigned aBase = sbase + aLd;
        const unsigned bBase = sbase + bLd;
#pragma unroll
        for (int ks = 0; ks < 2; ks++) {
            unsigned a0[4], a1[4];
            ldsm_x4(a0[0], a0[1], a0[2], a0[3], aBase + ks * 32u);
            ldsm_x4(a1[0], a1[1], a1[2], a1[3], aBase + 1280u + ks * 32u);
#pragma unroll
            for (int tj2 = 0; tj2 < 2; tj2++) {
                unsigned b[4];
                ldsm_x4(b[0], b[1], b[2], b[3], bBase + (unsigned)tj2 * 1280u + ks * 32u);
                mma16816(acc[0][2 * tj2],     a0, &b[0]);
                mma16816(acc[1][2 * tj2],     a1, &b[0]);
                mma16816(acc[0][2 * tj2 + 1], a0, &b[2]);
                mma16816(acc[1][2 * tj2 + 1], a1, &b[2]);
            }
        }
    }

#pragma unroll
    for (int ti = 0; ti < 2; ti++) {
#pragma unroll
        for (int tj = 0; tj < 4; tj++) {
            const size_t row = m0 + wm * 32 + ti * 16 + (lane >> 2);
            const int    col = wn * 32 + tj * 8 + (lane & 3) * 2;
            *(float2*)(out + row * 64 + col) =
                make_float2(acc[ti][tj][0], acc[ti][tj][1]);
            *(float2*)(out + (row + 8) * 64 + col) =
                make_float2(acc[ti][tj][2], acc[ti][tj][3]);
        }
    }
}

// ---------------------------------------------------------------------------
extern "C" void kernel_launch(void* const* d_in, const int* in_sizes, int n_in,
                              void* d_out, int out_size)
{
    (void)in_sizes; (void)n_in; (void)out_size;
    const float* q_in = (const float*)d_in[0];
    const float* k_in = (const float*)d_in[1];
    const float* v_in = (const float*)d_in[2];
    const float* Wq   = (const float*)d_in[3];
    const float* Wk   = (const float*)d_in[4];
    const float* Wv   = (const float*)d_in[5];
    const float* Wo   = (const float*)d_in[6];
    const int*   idx  = (const int*)d_in[7];
    float* out = (float*)d_out;

    cudaFuncSetAttribute(gemm_qkv_mma,
                         cudaFuncAttributeMaxDynamicSharedMemorySize, GEMM_SMEM);
    cudaFuncSetAttribute(out_gemm_mma,
                         cudaFuncAttributeMaxDynamicSharedMemorySize, OUT_SMEM);

    split_in<<<dim3(MROWS * DIN_ / (4 * 256), 3), 256>>>(q_in, k_in, v_in);
    split_w<<<dim3(DIN_ * HID_ / 256, 4), 256>>>(Wq, Wk, Wv, Wo);
    gemm_qkv_mma<<<dim3(HID_ / 128, MROWS / 128, 3), 128, GEMM_SMEM>>>();
    dot_kernel<<<(BH_ * L_) / 8, 256>>>(idx);
    topk_kernel<<<BH_, 256>>>();
    cumsum_kernel<<<BH_, 1024>>>();
    attn_part<<<dim3(BH_, NSPL), 256>>>();
    attn_merge<<<BH_, 256>>>();
    out_gemm_mma<<<MROWS / 128, 256, OUT_SMEM>>>(out);
}